// round 14
// baseline (speedup 1.0000x reference)
#include <cuda_runtime.h>
#include <cuda_fp16.h>
#include <mma.h>
#include <math.h>
#include <stdint.h>

using namespace nvcuda;

#define MAXN 100000
#define MAXE 1600000
#define SCAN_B 512

// Scratch (device globals; no cudaMalloc allowed)
__device__ __align__(16) __half g_bufH[MAXN * 64];    // t1 (pre-agg features, fp16)
__device__ __align__(16) __half g_bufH2[MAXN * 64];   // t2
__device__ __align__(16) int    g_deg[MAXN];
__device__ __align__(16) float  g_dinv[MAXN];
__device__ __align__(16) float  g_Wc[64 * 64];
__device__ __align__(16) float  g_bc[64];
__device__ __align__(16) int2   g_epk[MAXE];    // CSR slot: (src, norm-bits), grouped by dst
__device__ __align__(16) int    g_off[MAXN + 1];
__device__ __align__(16) int    g_cursor[MAXN];
__device__ __align__(16) int    g_bsum[1024];
__device__ int g_is32;

// Host-side aux resources, created once at program init.
struct HxAux {
    cudaStream_t s1;
    cudaEvent_t evF, evJ;
    HxAux() {
        cudaStreamCreateWithFlags(&s1, cudaStreamNonBlocking);
        cudaEventCreateWithFlags(&evF, cudaEventDisableTiming);
        cudaEventCreateWithFlags(&evJ, cudaEventDisableTiming);
    }
};
static HxAux g_aux;

// ---------------- dtype detection ----------------
__global__ void detect_kernel(const unsigned int* __restrict__ w, int nwords) {
    __shared__ int cnt;
    if (threadIdx.x == 0) cnt = 0;
    __syncthreads();
    int nz = 0;
    for (int i = threadIdx.x; i < 1024; i += blockDim.x) {
        int idx = 2 * i + 1;
        if (idx < nwords && w[idx] != 0u) nz++;
    }
    atomicAdd(&cnt, nz);
    __syncthreads();
    if (threadIdx.x == 0) g_is32 = (cnt > 10) ? 1 : 0;
}

// ---------------- prep ----------------

__global__ void zero4_kernel(float4* __restrict__ p, int n4) {
    int i = blockIdx.x * blockDim.x + threadIdx.x;
    if (i < n4) p[i] = make_float4(0.f, 0.f, 0.f, 0.f);
}

__global__ void count_deg_kernel(const void* __restrict__ ei, int E, int* __restrict__ deg) {
    int e = blockIdx.x * blockDim.x + threadIdx.x;
    if (e >= E) return;
    int d;
    if (g_is32) d = ((const int*)ei)[E + e];
    else        d = (int)((const long long*)ei)[E + e];
    atomicAdd(&deg[d], 1);
}

__global__ void scan1_kernel(const int* __restrict__ deg, int* __restrict__ off,
                             int* __restrict__ bsum, float* __restrict__ dinv, int n) {
    __shared__ int sh[SCAN_B];
    int i = blockIdx.x * SCAN_B + threadIdx.x;
    int v = (i < n) ? deg[i] : 0;
    if (i < n) dinv[i] = rsqrtf((float)v + 1.0f);
    sh[threadIdx.x] = v;
    __syncthreads();
    #pragma unroll
    for (int d = 1; d < SCAN_B; d <<= 1) {
        int t = 0;
        if ((int)threadIdx.x >= d) t = sh[threadIdx.x - d];
        __syncthreads();
        if ((int)threadIdx.x >= d) sh[threadIdx.x] += t;
        __syncthreads();
    }
    if (i < n) off[i] = sh[threadIdx.x] - v;
    if (threadIdx.x == SCAN_B - 1) bsum[blockIdx.x] = sh[threadIdx.x];
}

// scan3 with scan2 folded in: each block sums bsum[0..blockIdx) itself (nb <= 512).
__global__ void scan3_kernel(int* __restrict__ off, const int* __restrict__ bsum,
                             int* __restrict__ cursor, int n, int E, int nb) {
    __shared__ int sbase;
    if (threadIdx.x == 0) sbase = 0;
    __syncthreads();
    int v = ((int)threadIdx.x < blockIdx.x && (int)threadIdx.x < nb) ? bsum[threadIdx.x] : 0;
    #pragma unroll
    for (int d = 16; d >= 1; d >>= 1) v += __shfl_xor_sync(0xffffffffu, v, d);
    if ((threadIdx.x & 31) == 0 && v != 0) atomicAdd(&sbase, v);
    __syncthreads();
    int i = blockIdx.x * SCAN_B + threadIdx.x;
    if (i < n) {
        int o = off[i] + sbase;
        off[i] = o;
        cursor[i] = o;
    }
    if (i == 0) off[n] = E;
}

__global__ void fill_kernel(const void* __restrict__ ei, int E,
                            const float* __restrict__ dinv, int* __restrict__ cursor,
                            int2* __restrict__ epk) {
    int e = blockIdx.x * blockDim.x + threadIdx.x;
    if (e >= E) return;
    int s, d;
    if (g_is32) {
        const int* p = (const int*)ei;
        s = p[e];
        d = p[E + e];
    } else {
        const long long* p = (const long long*)ei;
        s = (int)p[e];
        d = (int)p[E + e];
    }
    int slot = atomicAdd(&cursor[d], 1);
    epk[slot] = make_int2(s, __float_as_int(dinv[s] * dinv[d]));
}

// Wc = W3 @ W4, bc = b3 @ W4 + b4 (fp32 exact)
__global__ void build_wc_kernel(const float* __restrict__ W3, const float* __restrict__ b3,
                                const float* __restrict__ W4, const float* __restrict__ b4,
                                float* __restrict__ Wc, float* __restrict__ bc) {
    int o = blockIdx.x * blockDim.x + threadIdx.x;
    if (o < 64 * 64) {
        int i = o >> 6, j = o & 63;
        float s = 0.f;
        #pragma unroll 8
        for (int k = 0; k < 256; k++) s = fmaf(W3[i * 256 + k], W4[k * 64 + j], s);
        Wc[o] = s;
    } else if (o < 64 * 64 + 64) {
        int j = o - 64 * 64;
        float s = b4[j];
        #pragma unroll 8
        for (int k = 0; k < 256; k++) s = fmaf(b3[k], W4[k * 64 + j], s);
        bc[j] = s;
    }
}

// ---------------- tf32 wmma GEMM (layer 1): Yh[n,64] = X[n,128] @ W[128,64], fp16 out ----

template <int K>
__global__ void __launch_bounds__(128, 2)
wmma_gemm_h_kernel(const float* __restrict__ X, const float* __restrict__ W,
                   __half* __restrict__ Y, int n) {
    extern __shared__ float sm[];
    const int LDX = K + 8;
    const int LDW = 64 + 8;
    float* Xs = sm;
    float* Ws = sm + 64 * LDX;

    const int t = threadIdx.x;
    const int row0 = blockIdx.x * 64;

    for (int i = t; i < K * 16; i += 128) {
        int r = i >> 4, c = i & 15;
        *(float4*)&Ws[r * LDW + c * 4] = ((const float4*)W)[i];
    }
    {
        const int QK = K / 4;
        for (int i = t; i < 64 * QK; i += 128) {
            int r = i / QK, q = i % QK;
            int row = row0 + r;
            float4 v = make_float4(0.f, 0.f, 0.f, 0.f);
            if (row < n) v = ((const float4*)X)[(size_t)row * QK + q];
            *(float4*)&Xs[r * LDX + q * 4] = v;
        }
    }
    __syncthreads();

    const int wid = t >> 5;

    wmma::fragment<wmma::accumulator, 16, 16, 8, float> acc[4];
    #pragma unroll
    for (int c = 0; c < 4; c++) wmma::fill_fragment(acc[c], 0.f);

    #pragma unroll
    for (int k = 0; k < K; k += 8) {
        wmma::fragment<wmma::matrix_a, 16, 16, 8, wmma::precision::tf32, wmma::row_major> a;
        wmma::load_matrix_sync(a, &Xs[(wid * 16) * LDX + k], LDX);
        #pragma unroll
        for (int i = 0; i < a.num_elements; i++) a.x[i] = wmma::__float_to_tf32(a.x[i]);
        #pragma unroll
        for (int c = 0; c < 4; c++) {
            wmma::fragment<wmma::matrix_b, 16, 16, 8, wmma::precision::tf32, wmma::row_major> b;
            wmma::load_matrix_sync(b, &Ws[k * LDW + c * 16], LDW);
            #pragma unroll
            for (int i = 0; i < b.num_elements; i++) b.x[i] = wmma::__float_to_tf32(b.x[i]);
            wmma::mma_sync(acc[c], a, b, acc[c]);
        }
    }

    __syncthreads();
    float* stage = sm;
    #pragma unroll
    for (int c = 0; c < 4; c++)
        wmma::store_matrix_sync(&stage[(wid * 16) * LDW + c * 16], acc[c], LDW, wmma::mem_row_major);
    __syncthreads();

    for (int i = t; i < 64 * 32; i += 128) {
        int r = i >> 5, c2 = i & 31;
        int row = row0 + r;
        if (row < n) {
            __half2 hv = __floats2half2_rn(stage[r * LDW + c2 * 2], stage[r * LDW + c2 * 2 + 1]);
            ((__half2*)Y)[(size_t)row * 32 + c2] = hv;
        }
    }
}

// ---------------- fused: agg(64 nodes) + relu -> 64x64 tf32 wmma (+softmax if FINAL) ------
// 512 threads = 16 warps. Warp w aggregates nodes {w, w+16, w+32, w+48} of the block's 64,
// writing relu'd rows into Xs. Then warps 0-3 do the 64x64x64 wmma.
// FINAL: epilogue = +bias_post, row log_softmax, fp32 out. Else: fp16 out.

template <bool FINAL>
__global__ void __launch_bounds__(512, 2)
fused_agg_wmma_kernel(const __half* __restrict__ h, const int* __restrict__ off,
                      const int2* __restrict__ epk, const float* __restrict__ dinv,
                      const float* __restrict__ bias_pre,
                      const float* __restrict__ W, const float* __restrict__ bias_post,
                      void* __restrict__ outv, int n) {
    extern __shared__ float sm[];
    const int LD = 72;
    float* Xs = sm;              // 64 * 72
    float* Ws = sm + 64 * LD;    // 64 * 72

    const int t = threadIdx.x;
    const int row0 = blockIdx.x * 64;

    // load W [64,64] -> Ws
    for (int i = t; i < 64 * 16; i += 512) {
        int r = i >> 4, c = i & 15;
        *(float4*)&Ws[r * LD + c * 4] = ((const float4*)W)[i];
    }

    const int wid = t >> 5;
    const int lane = t & 31;
    const int q = lane & 7;
    const int p = lane >> 3;
    const uint4* hv4 = (const uint4*)h;

    // aggregate 4 nodes per warp
    #pragma unroll
    for (int s = 0; s < 4; s++) {
        int row = wid + s * 16;
        int node = row0 + row;
        float2 a0 = make_float2(0.f, 0.f), a1 = a0, a2 = a0, a3 = a0;
        float2 c0 = a0, c1 = a0, c2 = a0, c3 = a0;
        if (node < n) {
            int beg = __ldg(&off[node]);
            int end = __ldg(&off[node + 1]);
            int i = beg + p;
            for (; i + 4 < end; i += 8) {
                int2 e0 = __ldg(&epk[i]);
                int2 e1 = __ldg(&epk[i + 4]);
                float w0 = __int_as_float(e0.y);
                float w1 = __int_as_float(e1.y);
                uint4 v0 = __ldg(&hv4[(size_t)e0.x * 8 + q]);
                uint4 v1 = __ldg(&hv4[(size_t)e1.x * 8 + q]);
                const __half2* p0 = (const __half2*)&v0;
                const __half2* p1 = (const __half2*)&v1;
                float2 f;
                f = __half22float2(p0[0]); a0.x = fmaf(f.x, w0, a0.x); a0.y = fmaf(f.y, w0, a0.y);
                f = __half22float2(p0[1]); a1.x = fmaf(f.x, w0, a1.x); a1.y = fmaf(f.y, w0, a1.y);
                f = __half22float2(p0[2]); a2.x = fmaf(f.x, w0, a2.x); a2.y = fmaf(f.y, w0, a2.y);
                f = __half22float2(p0[3]); a3.x = fmaf(f.x, w0, a3.x); a3.y = fmaf(f.y, w0, a3.y);
                f = __half22float2(p1[0]); c0.x = fmaf(f.x, w1, c0.x); c0.y = fmaf(f.y, w1, c0.y);
                f = __half22float2(p1[1]); c1.x = fmaf(f.x, w1, c1.x); c1.y = fmaf(f.y, w1, c1.y);
                f = __half22float2(p1[2]); c2.x = fmaf(f.x, w1, c2.x); c2.y = fmaf(f.y, w1, c2.y);
                f = __half22float2(p1[3]); c3.x = fmaf(f.x, w1, c3.x); c3.y = fmaf(f.y, w1, c3.y);
            }
            for (; i < end; i += 4) {
                int2 e0 = __ldg(&epk[i]);
                float w0 = __int_as_float(e0.y);
                uint4 v0 = __ldg(&hv4[(size_t)e0.x * 8 + q]);
                const __half2* p0 = (const __half2*)&v0;
                float2 f;
                f = __half22float2(p0[0]); a0.x = fmaf(f.x, w0, a0.x); a0.y = fmaf(f.y, w0, a0.y);
                f = __half22float2(p0[1]); a1.x = fmaf(f.x, w0, a1.x); a1.y = fmaf(f.y, w0, a1.y);
                f = __half22float2(p0[2]); a2.x = fmaf(f.x, w0, a2.x); a2.y = fmaf(f.y, w0, a2.y);
                f = __half22float2(p0[3]); a3.x = fmaf(f.x, w0, a3.x); a3.y = fmaf(f.y, w0, a3.y);
            }
        }
        a0.x += c0.x; a0.y += c0.y;  a1.x += c1.x; a1.y += c1.y;
        a2.x += c2.x; a2.y += c2.y;  a3.x += c3.x; a3.y += c3.y;
        #pragma unroll
        for (int d = 8; d <= 16; d <<= 1) {
            a0.x += __shfl_xor_sync(0xffffffffu, a0.x, d);
            a0.y += __shfl_xor_sync(0xffffffffu, a0.y, d);
            a1.x += __shfl_xor_sync(0xffffffffu, a1.x, d);
            a1.y += __shfl_xor_sync(0xffffffffu, a1.y, d);
            a2.x += __shfl_xor_sync(0xffffffffu, a2.x, d);
            a2.y += __shfl_xor_sync(0xffffffffu, a2.y, d);
            a3.x += __shfl_xor_sync(0xffffffffu, a3.x, d);
            a3.y += __shfl_xor_sync(0xffffffffu, a3.y, d);
        }
        if (p == 0) {
            float* xr = &Xs[row * LD];
            if (node < n) {
                float di = __ldg(&dinv[node]);
                float sl = di * di;
                uint4 sv = __ldg(&hv4[(size_t)node * 8 + q]);
                const __half2* sp = (const __half2*)&sv;
                float4 b0 = __ldg(((const float4*)bias_pre) + q * 2);
                float4 b1 = __ldg(((const float4*)bias_pre) + q * 2 + 1);
                float2 s0 = __half22float2(sp[0]);
                float2 s1 = __half22float2(sp[1]);
                float2 s2 = __half22float2(sp[2]);
                float2 s3 = __half22float2(sp[3]);
                float4 o0, o1;
                o0.x = fmaxf(fmaf(s0.x, sl, a0.x) + b0.x, 0.f);
                o0.y = fmaxf(fmaf(s0.y, sl, a0.y) + b0.y, 0.f);
                o0.z = fmaxf(fmaf(s1.x, sl, a1.x) + b0.z, 0.f);
                o0.w = fmaxf(fmaf(s1.y, sl, a1.y) + b0.w, 0.f);
                o1.x = fmaxf(fmaf(s2.x, sl, a2.x) + b1.x, 0.f);
                o1.y = fmaxf(fmaf(s2.y, sl, a2.y) + b1.y, 0.f);
                o1.z = fmaxf(fmaf(s3.x, sl, a3.x) + b1.z, 0.f);
                o1.w = fmaxf(fmaf(s3.y, sl, a3.y) + b1.w, 0.f);
                *(float4*)&xr[q * 8]     = o0;
                *(float4*)&xr[q * 8 + 4] = o1;
            } else {
                *(float4*)&xr[q * 8]     = make_float4(0.f, 0.f, 0.f, 0.f);
                *(float4*)&xr[q * 8 + 4] = make_float4(0.f, 0.f, 0.f, 0.f);
            }
        }
    }
    __syncthreads();

    // 64x64x64 wmma on warps 0-3 (each warp: its own 16 rows of Xs -> stores back over them)
    if (wid < 4) {
        wmma::fragment<wmma::accumulator, 16, 16, 8, float> acc[4];
        #pragma unroll
        for (int c = 0; c < 4; c++) wmma::fill_fragment(acc[c], 0.f);
        #pragma unroll
        for (int k = 0; k < 64; k += 8) {
            wmma::fragment<wmma::matrix_a, 16, 16, 8, wmma::precision::tf32, wmma::row_major> a;
            wmma::load_matrix_sync(a, &Xs[(wid * 16) * LD + k], LD);
            #pragma unroll
            for (int i = 0; i < a.num_elements; i++) a.x[i] = wmma::__float_to_tf32(a.x[i]);
            #pragma unroll
            for (int c = 0; c < 4; c++) {
                wmma::fragment<wmma::matrix_b, 16, 16, 8, wmma::precision::tf32, wmma::row_major> b;
                wmma::load_matrix_sync(b, &Ws[k * LD + c * 16], LD);
                #pragma unroll
                for (int i = 0; i < b.num_elements; i++) b.x[i] = wmma::__float_to_tf32(b.x[i]);
                wmma::mma_sync(acc[c], a, b, acc[c]);
            }
        }
        // safe: warp w writes only the 16 Xs rows it alone read as A
        #pragma unroll
        for (int c = 0; c < 4; c++)
            wmma::store_matrix_sync(&Xs[(wid * 16) * LD + c * 16], acc[c], LD, wmma::mem_row_major);
    }
    __syncthreads();

    if (FINAL) {
        if (t < 128) {
            int r = t >> 1;
            int hf = t & 1;
            float* sr = &Xs[r * LD + hf * 32];
            const float* bp = bias_post + hf * 32;
            float m = -1e30f;
            #pragma unroll
            for (int c = 0; c < 32; c++) {
                float v = sr[c] + bp[c];
                sr[c] = v;
                m = fmaxf(m, v);
            }
            m = fmaxf(m, __shfl_xor_sync(0xffffffffu, m, 1));
            float s = 0.f;
            #pragma unroll
            for (int c = 0; c < 32; c++) s += expf(sr[c] - m);
            s += __shfl_xor_sync(0xffffffffu, s, 1);
            float lse = m + logf(s);
            int row = row0 + r;
            if (row < n) {
                float4* Yv = (float4*)((float*)outv + (size_t)row * 64 + hf * 32);
                #pragma unroll
                for (int c4 = 0; c4 < 8; c4++) {
                    Yv[c4] = make_float4(sr[c4 * 4] - lse, sr[c4 * 4 + 1] - lse,
                                         sr[c4 * 4 + 2] - lse, sr[c4 * 4 + 3] - lse);
                }
            }
        }
    } else {
        __half* Y = (__half*)outv;
        for (int i = t; i < 64 * 32; i += 512) {
            int r = i >> 5, c2 = i & 31;
            int row = row0 + r;
            if (row < n) {
                __half2 hv = __floats2half2_rn(Xs[r * LD + c2 * 2], Xs[r * LD + c2 * 2 + 1]);
                ((__half2*)Y)[(size_t)row * 32 + c2] = hv;
            }
        }
    }
}

// ---------------- launcher ----------------

extern "C" void kernel_launch(void* const* d_in, const int* in_sizes, int n_in,
                              void* d_out, int out_size) {
    const float* x  = (const float*)d_in[0];
    const void*  ei = d_in[1];
    const float* W1 = (const float*)d_in[2];
    const float* b1 = (const float*)d_in[3];
    const float* W2 = (const float*)d_in[4];
    const float* b2 = (const float*)d_in[5];
    const float* W3 = (const float*)d_in[6];
    const float* b3 = (const float*)d_in[7];
    const float* W4 = (const float*)d_in[8];
    const float* b4 = (const float*)d_in[9];
    float* out = (float*)d_out;

    const int n = in_sizes[0] / 128;
    const int E = in_sizes[1] / 2;

    float *dinv, *Wc, *bc;
    __half *bufH, *bufH2;
    int *deg, *off, *cursor, *bsum;
    int2* epk;
    cudaGetSymbolAddress((void**)&bufH,  g_bufH);
    cudaGetSymbolAddress((void**)&bufH2, g_bufH2);
    cudaGetSymbolAddress((void**)&deg,   g_deg);
    cudaGetSymbolAddress((void**)&dinv,  g_dinv);
    cudaGetSymbolAddress((void**)&Wc,    g_Wc);
    cudaGetSymbolAddress((void**)&bc,    g_bc);
    cudaGetSymbolAddress((void**)&epk,   g_epk);
    cudaGetSymbolAddress((void**)&off,   g_off);
    cudaGetSymbolAddress((void**)&cursor, g_cursor);
    cudaGetSymbolAddress((void**)&bsum,  g_bsum);

    const int SMW128 = (64 * (128 + 8) + 128 * (64 + 8)) * 4;  // 71680 B
    const int SMF    = (64 * 72 * 2) * 4;                      // 36864 B
    cudaFuncSetAttribute((const void*)wmma_gemm_h_kernel<128>,      cudaFuncAttributeMaxDynamicSharedMemorySize, SMW128);
    cudaFuncSetAttribute((const void*)fused_agg_wmma_kernel<false>, cudaFuncAttributeMaxDynamicSharedMemorySize, SMF);
    cudaFuncSetAttribute((const void*)fused_agg_wmma_kernel<true>,  cudaFuncAttributeMaxDynamicSharedMemorySize, SMF);

    const int nThreads = 256;
    const int nScanBlocks = (n + SCAN_B - 1) / SCAN_B;
    const int fusedBlocks = (n + 63) / 64;

    // ---- fork: side stream runs GEMM1 + build_wc while main stream builds the CSR ----
    cudaEventRecord(g_aux.evF, 0);
    cudaStreamWaitEvent(g_aux.s1, g_aux.evF, 0);

    wmma_gemm_h_kernel<128><<<fusedBlocks, 128, SMW128, g_aux.s1>>>(x, W1, bufH, n);
    build_wc_kernel<<<(64 * 64 + 64 + nThreads - 1) / nThreads, nThreads, 0, g_aux.s1>>>(W3, b3, W4, b4, Wc, bc);

    detect_kernel<<<1, 256>>>((const unsigned int*)ei, 2048);
    zero4_kernel<<<((n + 3) / 4 + nThreads - 1) / nThreads, nThreads>>>((float4*)deg, (n + 3) / 4);
    count_deg_kernel<<<(E + nThreads - 1) / nThreads, nThreads>>>(ei, E, deg);
    scan1_kernel<<<nScanBlocks, SCAN_B>>>(deg, off, bsum, dinv, n);
    scan3_kernel<<<nScanBlocks, SCAN_B>>>(off, bsum, cursor, n, E, nScanBlocks);
    fill_kernel<<<(E + nThreads - 1) / nThreads, nThreads>>>(ei, E, dinv, cursor, epk);

    // ---- join ----
    cudaEventRecord(g_aux.evJ, g_aux.s1);
    cudaStreamWaitEvent(0, g_aux.evJ, 0);

    // ---- fused layer 2: h1 = relu(agg(t1)+b1); t2 = h1 @ W2 (fp16) ----
    fused_agg_wmma_kernel<false><<<fusedBlocks, 512, SMF>>>(bufH, off, epk, dinv, b1, W2, nullptr, bufH2, n);

    // ---- fused layers 3+4: h2 = relu(agg(t2)+b2); out = log_softmax(h2 @ Wc + bc) ----
    fused_agg_wmma_kernel<true><<<fusedBlocks, 512, SMF>>>(bufH2, off, epk, dinv, b2, Wc, bc, out, n);
}